// round 11
// baseline (speedup 1.0000x reference)
#include <cuda_runtime.h>
#include <math.h>

#define VDIM 1024
#define MAXB 8
#define MAXT 256
#define MAXU 65
#define DPS  66          // padded row stride in shared (<=2-way bank conflict on diagonals)
#define NEG_BIG (-1.0e30f)

// Scratch (allocation-free rule: __device__ globals). Values stored in LOG2 domain.
__device__ float g_lp_blank[MAXB * MAXT * MAXU];          // [b][t][u]   (log2)
__device__ float g_lp_label[MAXB * MAXT * (MAXU - 1)];    // [b][t][u]   (log2)
__device__ float g_loss[MAXB];
__device__ int   g_done = 0;

__device__ __forceinline__ float ex2f(float x) { float r; asm("ex2.approx.f32 %0,%1;" : "=f"(r) : "f"(x)); return r; }
__device__ __forceinline__ float lg2f(float x) { float r; asm("lg2.approx.f32 %0,%1;" : "=f"(r) : "f"(x)); return r; }

// log2-domain logaddexp: log2(2^x + 2^y)
__device__ __forceinline__ float l2add(float x, float y)
{
    float mx = fmaxf(x, y);
    float mn = fminf(x, y);
    return mx + lg2f(1.f + ex2f(mn - mx));
}

// ---------------------------------------------------------------------------
// Kernel 1: per-row log-softmax over V=1024, COMPACTED over the active set
// {(b,t,u): t < act_len[b], u <= label_len[b]}. One warp per compact row.
// ---------------------------------------------------------------------------
__global__ void __launch_bounds__(256) softmax_pick_kernel(
    const float* __restrict__ acts, const int* __restrict__ labels,
    const int* __restrict__ act_lens, const int* __restrict__ label_lens,
    int B, int T, int U)
{
    const float LOG2E = 1.44269504088896340736f;

    int gw   = (blockIdx.x * blockDim.x + threadIdx.x) >> 5;  // compact row index
    int lane = threadIdx.x & 31;

    // decode compact index -> (b,t,u)
    int rem = gw;
    int b = -1, t = 0, u = 0;
#pragma unroll
    for (int bb = 0; bb < MAXB; ++bb) {
        if (bb >= B) break;
        int cu  = __ldg(&label_lens[bb]) + 1;
        int cnt = __ldg(&act_lens[bb]) * cu;
        if (b < 0) {
            if (rem < cnt) { b = bb; t = rem / cu; u = rem - t * cu; }
            else rem -= cnt;
        }
    }
    if (b < 0) return;               // past the active set

    int rowIdx = (b * T + t) * U + u;
    const float4* row = reinterpret_cast<const float4*>(acts) + (size_t)rowIdx * (VDIM / 4);

    float4 v[8];
#pragma unroll
    for (int k = 0; k < 8; ++k)
        v[k] = row[lane + 32 * k];

    float m = -INFINITY;
#pragma unroll
    for (int k = 0; k < 8; ++k)
        m = fmaxf(m, fmaxf(fmaxf(v[k].x, v[k].y), fmaxf(v[k].z, v[k].w)));
#pragma unroll
    for (int o = 16; o > 0; o >>= 1)
        m = fmaxf(m, __shfl_xor_sync(0xffffffffu, m, o));

    float s = 0.f;
#pragma unroll
    for (int k = 0; k < 8; ++k) {
        s += __expf(v[k].x - m);
        s += __expf(v[k].y - m);
        s += __expf(v[k].z - m);
        s += __expf(v[k].w - m);
    }
#pragma unroll
    for (int o = 16; o > 0; o >>= 1)
        s += __shfl_xor_sync(0xffffffffu, s, o);

    float logZ = m + __logf(s);

    if (lane == 0)
        g_lp_blank[rowIdx] = (v[0].x - logZ) * LOG2E;

    if (u < U - 1) {
        int lbl = labels[b * (U - 1) + u];
        int q   = lbl >> 2;
        if (lane == (q & 31)) {
            int kq = q >> 5;
            int c  = lbl & 3;
#pragma unroll
            for (int k = 0; k < 8; ++k)
                if (k == kq) {
                    float4 w = v[k];
                    float  x = (c == 0) ? w.x : (c == 1) ? w.y : (c == 2) ? w.z : w.w;
                    g_lp_label[(b * T + t) * (U - 1) + u] = (x - logZ) * LOG2E;
                }
        }
    }
}

// ---------------------------------------------------------------------------
// Kernel 2: alpha wavefront DP (one block per batch, DP in warp 0) + fused
// final reduction via last-block-done atomic.
// Layout (one-sided sentinels, R8):
//   sb[r][u] = lpb(r-1,u) for r in [1,tcap+1]; row 0 = NEG_BIG sentinel.
//   sl[t][c] = lpl(t,c-1) for t in [0,tcap], c in [1,64]; col 0 = NEG_BIG.
// Rows beyond tcap+1 are left stale/uninit: only cells with t > tcap ever read
// them, and those cells never flow into the captured (tcap,ucap) value.
// DP loop is split in 3 phases; the middle phase (d in [64,255]) is provably
// in-range for every slot -> six pure pointer streams, zero clamps.
// ---------------------------------------------------------------------------
extern __shared__ __align__(16) float smem2[];

__global__ void __launch_bounds__(256) alpha_kernel(
    const int* __restrict__ act_lens, const int* __restrict__ label_lens,
    float* __restrict__ out, int T, int U, int B)
{
    const float LN2 = 0.69314718055994530942f;

    int b    = blockIdx.x;
    int tid  = threadIdx.x;
    int lane = tid & 31;
    int warp = tid >> 5;
    int U1   = U - 1;

    float* sb = smem2;                    // (T+1) x DPS
    float* sl = smem2 + (T + 1) * DPS;    // T x DPS

    const float* gb = g_lp_blank + (size_t)b * T * U;
    const float* gl = g_lp_label + (size_t)b * T * U1;

    int tcap = __ldg(&act_lens[b]) - 1;
    int ucap = __ldg(&label_lens[b]);

    // preload only rows the DP's valid region touches
    for (int r = warp; r <= tcap + 1; r += 8) {
        float* dst = sb + r * DPS;
        if (r == 0) {
            for (int u = lane; u < U; u += 32) dst[u] = NEG_BIG;
        } else {
            const float* src = gb + (r - 1) * U;
            for (int u = lane; u < U; u += 32) dst[u] = src[u];
        }
    }
    int slmax = min(tcap, T - 1);
    for (int r = warp; r <= slmax; r += 8) {
        float* dst = sl + r * DPS;
        if (lane == 0) dst[0] = NEG_BIG;
        for (int c = lane; c < U1; c += 32) dst[1 + c] = gl[r * U1 + c];
    }
    __syncthreads();

    if (tid >= 32) return;

    int l  = tid;
    int u0 = 2 * l, u1 = 2 * l + 1;          // lane 31 also owns u=64 (slot 2)

    float a0 = 0.f, a1 = 0.f, a2 = 0.f;      // alpha at current diagonal (log2)
    float r0 = 0.f, r1 = 0.f, r2 = 0.f;      // captured alpha(tcap, u)

    int d0cap = tcap + u0;
    int d1cap = tcap + u1;
    int d2cap = tcap + 64;
    int D     = tcap + ucap;                 // last diagonal needed

    // ---- phase 1: d in [1, min(63, D)] — clamped addressing ----
    int p1end = min(63, D);
    for (int d = 1; d <= p1end; ++d) {
        float p = __shfl_up_sync(0xffffffffu, a1, 1);

        int t0 = d - u0; int c0 = min(max(t0, 0), T); int m0 = min(c0, T - 1);
        int t1 = d - u1; int c1 = min(max(t1, 0), T); int m1 = min(c1, T - 1);
        int t2 = d - 64; int c2 = min(max(t2, 0), T); int m2 = min(c2, T - 1);

        float n0 = l2add(a0 + sb[c0 * DPS + u0], p  + sl[m0 * DPS + u0]);
        float n1 = l2add(a1 + sb[c1 * DPS + u1], a0 + sl[m1 * DPS + u1]);
        float n2 = l2add(a2 + sb[c2 * DPS + 64], a1 + sl[m2 * DPS + 64]);

        r0 = (d == d0cap) ? n0 : r0;
        r1 = (d == d1cap) ? n1 : r1;
        r2 = (d == d2cap) ? n2 : r2;
        a0 = n0; a1 = n1; a2 = n2;
    }

    // ---- phase 2: d in [64, min(255, D)] — clamp-free pointer streams ----
    // for all slots: t = d-u with d in [64,255], u in [0,64] => t in [0,255]:
    // sb row index in [0,T] OK (row 0 = sentinel), sl row index in [0,T-1] OK.
    int p2end = min(T - 1, D);
    {
        const float* pb0 = sb + (64 - u0) * DPS + u0;
        const float* pl0 = sl + (64 - u0) * DPS + u0;
        const float* pb1 = sb + (64 - u1) * DPS + u1;
        const float* pl1 = sl + (64 - u1) * DPS + u1;
        const float* pb2 = sb + 64;              // row 0, col 64
        const float* pl2 = sl + 64;

        float vb0 = pb0[0], vl0 = pl0[0];
        float vb1 = pb1[0], vl1 = pl1[0];
        float vb2 = pb2[0], vl2 = pl2[0];

#pragma unroll 4
        for (int d = 64; d <= p2end; ++d) {
            float nvb0 = pb0[DPS], nvl0 = pl0[DPS];
            float nvb1 = pb1[DPS], nvl1 = pl1[DPS];
            float nvb2 = pb2[DPS], nvl2 = pl2[DPS];
            pb0 += DPS; pl0 += DPS; pb1 += DPS; pl1 += DPS; pb2 += DPS; pl2 += DPS;

            float p = __shfl_up_sync(0xffffffffu, a1, 1);

            float n0 = l2add(a0 + vb0, p  + vl0);
            float n1 = l2add(a1 + vb1, a0 + vl1);
            float n2 = l2add(a2 + vb2, a1 + vl2);

            r0 = (d == d0cap) ? n0 : r0;
            r1 = (d == d1cap) ? n1 : r1;
            r2 = (d == d2cap) ? n2 : r2;

            a0 = n0; a1 = n1; a2 = n2;
            vb0 = nvb0; vl0 = nvl0; vb1 = nvb1; vl1 = nvl1; vb2 = nvb2; vl2 = nvl2;
        }
    }

    // ---- phase 3: d in [256, D] — clamped addressing ----
    for (int d = T; d <= D; ++d) {
        float p = __shfl_up_sync(0xffffffffu, a1, 1);

        int t0 = d - u0; int c0 = min(max(t0, 0), T); int m0 = min(c0, T - 1);
        int t1 = d - u1; int c1 = min(max(t1, 0), T); int m1 = min(c1, T - 1);
        int t2 = d - 64; int c2 = min(max(t2, 0), T); int m2 = min(c2, T - 1);

        float n0 = l2add(a0 + sb[c0 * DPS + u0], p  + sl[m0 * DPS + u0]);
        float n1 = l2add(a1 + sb[c1 * DPS + u1], a0 + sl[m1 * DPS + u1]);
        float n2 = l2add(a2 + sb[c2 * DPS + 64], a1 + sl[m2 * DPS + 64]);

        r0 = (d == d0cap) ? n0 : r0;
        r1 = (d == d1cap) ? n1 : r1;
        r2 = (d == d2cap) ? n2 : r2;
        a0 = n0; a1 = n1; a2 = n2;
    }

    // exactly one (lane, slot) owns (tcap, ucap)
    float res = 0.f; int hit = 0;
    if (u0 == ucap)                  { res = r0; hit = 1; }
    else if (u1 == ucap)             { res = r1; hit = 1; }
    else if (l == 31 && ucap == 64)  { res = r2; hit = 1; }
    if (hit)
        g_loss[b] = -(res + sb[(tcap + 1) * DPS + ucap]) * LN2;

    // ---- fused finalize: last block to arrive reduces and resets ----
    __syncwarp();
    __threadfence();
    if (lane == 0) {
        int old = atomicAdd(&g_done, 1);
        if (old == gridDim.x - 1) {
            float s = 0.f;
            for (int i = 0; i < B; ++i) s += g_loss[i];
            out[0] = s / (float)B;
            g_done = 0;                       // reset for next graph replay
        }
    }
}

// ---------------------------------------------------------------------------
extern "C" void kernel_launch(void* const* d_in, const int* in_sizes, int n_in,
                              void* d_out, int out_size)
{
    const float* acts       = (const float*)d_in[0];
    const int*   labels     = (const int*)d_in[1];
    const int*   act_lens   = (const int*)d_in[2];
    const int*   label_lens = (const int*)d_in[3];

    int B  = in_sizes[2];                 // 8
    int U1 = in_sizes[1] / B;             // 64
    int U  = U1 + 1;                      // 65
    long long total = in_sizes[0];
    int T  = (int)(total / ((long long)B * U * VDIM));   // 256

    // upper-bound grid; warps past the compacted active set exit immediately
    int nRows = B * T * U;
    int blocks = (nRows + 7) / 8;
    softmax_pick_kernel<<<blocks, 256>>>(acts, labels, act_lens, label_lens,
                                         B, T, U);

    int smemBytes = ((T + 1) + T) * DPS * (int)sizeof(float);   // 135,432 B
    cudaFuncSetAttribute(alpha_kernel,
                         cudaFuncAttributeMaxDynamicSharedMemorySize, smemBytes);
    alpha_kernel<<<B, 256, smemBytes>>>(act_lens, label_lens, (float*)d_out,
                                        T, U, B);
}

// round 16
// speedup vs baseline: 1.0610x; 1.0610x over previous
#include <cuda_runtime.h>
#include <math.h>

#define VDIM 1024
#define MAXB 8
#define MAXT 256
#define MAXU 65
#define DST  66                  // diagonal-row stride (floats)
#define BROWS 322                // B rows: d in [0, 321]
#define LROWS 322                // L rows: d in [0, 319] + prefetch slack (row 320)
#define NEG_BIG (-1.0e30f)

// Scratch (allocation-free rule: __device__ globals). Values stored in LOG2 domain.
__device__ float g_lp_blank[MAXB * MAXT * MAXU];          // [b][t][u]   (log2)
__device__ float g_lp_label[MAXB * MAXT * (MAXU - 1)];    // [b][t][u]   (log2)
__device__ float g_loss[MAXB];
__device__ int   g_done = 0;

__device__ __forceinline__ float ex2f(float x) { float r; asm("ex2.approx.f32 %0,%1;" : "=f"(r) : "f"(x)); return r; }
__device__ __forceinline__ float lg2f(float x) { float r; asm("lg2.approx.f32 %0,%1;" : "=f"(r) : "f"(x)); return r; }

// log2-domain logaddexp: log2(2^x + 2^y)
__device__ __forceinline__ float l2add(float x, float y)
{
    float mx = fmaxf(x, y);
    float mn = fminf(x, y);
    return mx + lg2f(1.f + ex2f(mn - mx));
}

// ---------------------------------------------------------------------------
// Kernel 1: per-row log-softmax over V=1024, COMPACTED over the active set
// {(b,t,u): t < act_len[b], u <= label_len[b]}. One warp per compact row.
// ---------------------------------------------------------------------------
__global__ void __launch_bounds__(256) softmax_pick_kernel(
    const float* __restrict__ acts, const int* __restrict__ labels,
    const int* __restrict__ act_lens, const int* __restrict__ label_lens,
    int B, int T, int U)
{
    const float LOG2E = 1.44269504088896340736f;

    int gw   = (blockIdx.x * blockDim.x + threadIdx.x) >> 5;  // compact row index
    int lane = threadIdx.x & 31;

    // decode compact index -> (b,t,u)
    int rem = gw;
    int b = -1, t = 0, u = 0;
#pragma unroll
    for (int bb = 0; bb < MAXB; ++bb) {
        if (bb >= B) break;
        int cu  = __ldg(&label_lens[bb]) + 1;
        int cnt = __ldg(&act_lens[bb]) * cu;
        if (b < 0) {
            if (rem < cnt) { b = bb; t = rem / cu; u = rem - t * cu; }
            else rem -= cnt;
        }
    }
    if (b < 0) return;               // past the active set

    int rowIdx = (b * T + t) * U + u;
    const float4* row = reinterpret_cast<const float4*>(acts) + (size_t)rowIdx * (VDIM / 4);

    float4 v[8];
#pragma unroll
    for (int k = 0; k < 8; ++k)
        v[k] = row[lane + 32 * k];

    float m = -INFINITY;
#pragma unroll
    for (int k = 0; k < 8; ++k)
        m = fmaxf(m, fmaxf(fmaxf(v[k].x, v[k].y), fmaxf(v[k].z, v[k].w)));
#pragma unroll
    for (int o = 16; o > 0; o >>= 1)
        m = fmaxf(m, __shfl_xor_sync(0xffffffffu, m, o));

    float s = 0.f;
#pragma unroll
    for (int k = 0; k < 8; ++k) {
        s += __expf(v[k].x - m);
        s += __expf(v[k].y - m);
        s += __expf(v[k].z - m);
        s += __expf(v[k].w - m);
    }
#pragma unroll
    for (int o = 16; o > 0; o >>= 1)
        s += __shfl_xor_sync(0xffffffffu, s, o);

    float logZ = m + __logf(s);

    if (lane == 0)
        g_lp_blank[rowIdx] = (v[0].x - logZ) * LOG2E;

    if (u < U - 1) {
        int lbl = labels[b * (U - 1) + u];
        int q   = lbl >> 2;
        if (lane == (q & 31)) {
            int kq = q >> 5;
            int c  = lbl & 3;
#pragma unroll
            for (int k = 0; k < 8; ++k)
                if (k == kq) {
                    float4 w = v[k];
                    float  x = (c == 0) ? w.x : (c == 1) ? w.y : (c == 2) ? w.z : w.w;
                    g_lp_label[(b * T + t) * (U - 1) + u] = (x - logZ) * LOG2E;
                }
        }
    }
}

// ---------------------------------------------------------------------------
// Kernel 2: alpha wavefront DP, DIAGONAL-MAJOR operand layout.
//   B[d][u] = lpb(d-u-1, u)   (blank operand of cell t=d-u, u)
//   L[d][u] = lpl(d-u,  u-1)  (label operand of cell t=d-u, u)
// Per diagonal, all operands live in two contiguous smem rows:
//   lane l: float2 at B[d*66+2l], float2 at L[d*66+2l], scalars at col 64.
// -> 4 LDS + 1 IADD per iteration, tiny live set (fits 32 regs), no clamps.
// Sentinels: rows 0..63 bulk-filled NEG_BIG (all t<0 reads), B[u][u]=NEG_BIG
// (t=0 edge), L[*][0]=NEG_BIG (u=0 edge). Cells with t>tcap / u>ucap read
// garbage but dependencies only flow toward higher t/u, so it is contained.
// Both arrays padded to 322 rows: the d+1 prefetch at the last diagonal
// (d = 319) touches row 320 and must stay in-bounds.
// Fused final reduction via last-block-done atomic.
// ---------------------------------------------------------------------------
extern __shared__ __align__(16) float smem2[];

__global__ void __launch_bounds__(256) alpha_kernel(
    const int* __restrict__ act_lens, const int* __restrict__ label_lens,
    float* __restrict__ out, int T, int U, int B)
{
    const float LN2 = 0.69314718055994530942f;

    int b    = blockIdx.x;
    int tid  = threadIdx.x;
    int lane = tid & 31;
    int warp = tid >> 5;
    int U1   = U - 1;

    float* Bd = smem2;                 // BROWS x DST
    float* Ld = smem2 + BROWS * DST;   // LROWS x DST

    const float* gb = g_lp_blank + (size_t)b * T * U;
    const float* gl = g_lp_label + (size_t)b * T * U1;

    int tcap = __ldg(&act_lens[b]) - 1;
    int ucap = __ldg(&label_lens[b]);
    int D    = tcap + ucap;

    // ---- phase A: sentinel fills ----
    for (int i = tid; i < 64 * DST; i += 256) Bd[i] = NEG_BIG;   // rows 0..63
    for (int i = tid; i < 64 * DST; i += 256) Ld[i] = NEG_BIG;
    if (tid <= 64) Bd[tid * DST + tid] = NEG_BIG;                // t=0 stripe
    for (int r = 64 + tid; r < LROWS; r += 256) Ld[r * DST] = NEG_BIG; // u=0 col
    __syncthreads();

    // ---- phase B: data writes (overwrite bulk-filled cells where valid) ----
    // B[(t+1+u)][u] = lpb(t,u), t in [0,tcap]  (max row 320 < 322)
    for (int t = warp; t <= tcap; t += 8) {
        const float* src = gb + t * U;
        for (int u = lane; u < U; u += 32)
            Bd[(t + 1 + u) * DST + u] = src[u];
    }
    // L[(t+c+1)][c+1] = lpl(t,c), t in [0,min(tcap,T-1)]  (max row 319)
    int slmax = min(tcap, T - 1);
    for (int t = warp; t <= slmax; t += 8) {
        const float* src = gl + t * U1;
        for (int c = lane; c < U1; c += 32)
            Ld[(t + c + 1) * DST + (c + 1)] = src[c];
    }
    __syncthreads();

    if (tid >= 32) return;

    int l  = tid;
    int u0 = 2 * l, u1 = 2 * l + 1;          // lane 31 also owns u=64 (slot 2)

    float a0 = 0.f, a1 = 0.f, a2 = 0.f;      // alpha at current diagonal (log2)
    float r0 = 0.f, r1 = 0.f, r2 = 0.f;      // captured alpha(tcap, u)

    int d0cap = tcap + u0;
    int d1cap = tcap + u1;
    int d2cap = tcap + 64;

    int off = DST + 2 * l;                   // d = 1 row, this lane's pair
    float2 vb  = *reinterpret_cast<const float2*>(Bd + off);
    float2 vl  = *reinterpret_cast<const float2*>(Ld + off);
    float  vb2 = Bd[DST + 64];
    float  vl2 = Ld[DST + 64];

#pragma unroll 4
    for (int d = 1; d <= D; ++d) {
        // prefetch next diagonal's operands (independent of this chain);
        // max row touched = D+1 = 320 < 322 for both arrays
        float2 nvb  = *reinterpret_cast<const float2*>(Bd + off + DST);
        float2 nvl  = *reinterpret_cast<const float2*>(Ld + off + DST);
        float  nvb2 = Bd[off - 2 * l + DST + 64];
        float  nvl2 = Ld[off - 2 * l + DST + 64];
        off += DST;

        float p = __shfl_up_sync(0xffffffffu, a1, 1);   // alpha(.., u0-1) from lane l-1

        float n0 = l2add(a0 + vb.x, p  + vl.x);
        float n1 = l2add(a1 + vb.y, a0 + vl.y);
        float n2 = l2add(a2 + vb2,  a1 + vl2);

        r0 = (d == d0cap) ? n0 : r0;
        r1 = (d == d1cap) ? n1 : r1;
        r2 = (d == d2cap) ? n2 : r2;

        a0 = n0; a1 = n1; a2 = n2;
        vb = nvb; vl = nvl; vb2 = nvb2; vl2 = nvl2;
    }

    // exactly one (lane, slot) owns (tcap, ucap); final blank = B[D+1][ucap]
    float res = 0.f; int hit = 0;
    if (u0 == ucap)                  { res = r0; hit = 1; }
    else if (u1 == ucap)             { res = r1; hit = 1; }
    else if (l == 31 && ucap == 64)  { res = r2; hit = 1; }
    if (hit)
        g_loss[b] = -(res + Bd[(D + 1) * DST + ucap]) * LN2;

    // ---- fused finalize: last block to arrive reduces and resets ----
    __syncwarp();
    __threadfence();
    if (lane == 0) {
        int old = atomicAdd(&g_done, 1);
        if (old == gridDim.x - 1) {
            float s = 0.f;
            for (int i = 0; i < B; ++i) s += g_loss[i];
            out[0] = s / (float)B;
            g_done = 0;                       // reset for next graph replay
        }
    }
}

// ---------------------------------------------------------------------------
extern "C" void kernel_launch(void* const* d_in, const int* in_sizes, int n_in,
                              void* d_out, int out_size)
{
    const float* acts       = (const float*)d_in[0];
    const int*   labels     = (const int*)d_in[1];
    const int*   act_lens   = (const int*)d_in[2];
    const int*   label_lens = (const int*)d_in[3];

    int B  = in_sizes[2];                 // 8
    int U1 = in_sizes[1] / B;             // 64
    int U  = U1 + 1;                      // 65
    long long total = in_sizes[0];
    int T  = (int)(total / ((long long)B * U * VDIM));   // 256

    // upper-bound grid; warps past the compacted active set exit immediately
    int nRows = B * T * U;
    int blocks = (nRows + 7) / 8;
    softmax_pick_kernel<<<blocks, 256>>>(acts, labels, act_lens, label_lens,
                                         B, T, U);

    int smemBytes = (BROWS + LROWS) * DST * (int)sizeof(float);   // 170,016 B
    cudaFuncSetAttribute(alpha_kernel,
                         cudaFuncAttributeMaxDynamicSharedMemorySize, smemBytes);
    alpha_kernel<<<B, 256, smemBytes>>>(act_lens, label_lens, (float*)d_out,
                                        T, U, B);
}